// round 12
// baseline (speedup 1.0000x reference)
#include <cuda_runtime.h>

#define HID 8192
#define BATCH 512
#define NIN 16
#define RANK 8
#define NOUT 4
#define GRID 256
#define TPB 512

// u partials: two H-halves, folded in phase 2 (fixed order => deterministic)
__device__ float g_u_part[2][BATCH * RANK];
__device__ unsigned int g_bar;   // monotone ticket counter, never reset (replay-safe)

typedef unsigned long long ull;

__device__ __forceinline__ void ffma2(ull& d, ull a, ull b) {
    asm("fma.rn.f32x2 %0, %1, %2, %0;" : "+l"(d) : "l"(a), "l"(b));
}
__device__ __forceinline__ void unpack2(float& lo, float& hi, ull v) {
    asm("mov.b64 {%0, %1}, %2;" : "=f"(lo), "=f"(hi) : "l"(v));
}
__device__ __forceinline__ ull pack2(float lo, float hi) {
    ull v;
    asm("mov.b64 %0, {%1, %2};" : "=l"(v) : "f"(lo), "f"(hi));
    return v;
}

__device__ __forceinline__ void grid_barrier() {
    __syncthreads();
    if (threadIdx.x == 0) {
        __threadfence();
        unsigned int old = atomicAdd(&g_bar, 1u);
        unsigned int target = (old / GRID + 1u) * GRID;
        while ((int)(*(volatile unsigned int*)&g_bar - target) < 0)
            __nanosleep(32);
        __threadfence();
    }
    __syncthreads();
}

__global__ void __launch_bounds__(TPB, 2) k_fused(const float* __restrict__ input,
                                                  const float* __restrict__ hidden,
                                                  const float* __restrict__ Win,
                                                  const float* __restrict__ L,
                                                  const float* __restrict__ R,
                                                  const float* __restrict__ Wout,
                                                  float* __restrict__ nh,
                                                  float* __restrict__ out) {
    const int t = threadIdx.x;
    const int lane = t & 31, w = t >> 5;    // 16 warps

    __shared__ float red[16][16];
    __shared__ __align__(16) float comb[32][24];   // phase 2: [input(16) | u(8)]

    // ========== Phase 1: u partials; r split; f32x2 accumulation ==========
    {
        const int bg = blockIdx.x >> 1;          // 0..127 -> 4 batch rows
        const int half = blockIdx.x & 1;         // H-half
        const int bbase = bg * 4;
        const int rh = t >> 8;                   // 0..1 -> r in [rh*4, rh*4+4)
        const int tt = t & 255;

        ull accp[16];                            // accp[bl*4+rr] = (even-j, odd-j)
#pragma unroll
        for (int i = 0; i < 16; i++) accp[i] = 0ULL;

#pragma unroll
        for (int it = 0; it < 4; it++) {
            const int j = half * 4096 + it * 1024 + tt * 4;
            float4 h4[4];
#pragma unroll
            for (int bl = 0; bl < 4; bl++)
                h4[bl] = *(const float4*)(hidden + (bbase + bl) * HID + j);
            ull thp[4][2];
#pragma unroll
            for (int bl = 0; bl < 4; bl++) {
                thp[bl][0] = pack2(__tanhf(h4[bl].x), __tanhf(h4[bl].y));
                thp[bl][1] = pack2(__tanhf(h4[bl].z), __tanhf(h4[bl].w));
            }
#pragma unroll
            for (int rr = 0; rr < 4; rr++) {
                union { float4 f; ull p[2]; } rv;
                rv.f = *(const float4*)(R + (rh * 4 + rr) * HID + j);
#pragma unroll
                for (int bl = 0; bl < 4; bl++) {
                    ffma2(accp[bl * 4 + rr], thp[bl][0], rv.p[0]);
                    ffma2(accp[bl * 4 + rr], thp[bl][1], rv.p[1]);
                }
            }
        }

        // collapse pairs -> 16 scalars
        float acc[16];
#pragma unroll
        for (int i = 0; i < 16; i++) {
            float lo, hi;
            unpack2(lo, hi, accp[i]);
            acc[i] = lo + hi;
        }

        // fold 16 values over lane bits 0..3 (15 SHFL), then reduce bit 4
#pragma unroll
        for (int m = 8; m >= 1; m >>= 1) {
            const bool up = (lane & m) != 0;
#pragma unroll
            for (int i = 0; i < m; i++) {
                float send = up ? acc[i] : acc[i + m];
                float got = __shfl_xor_sync(0xffffffffu, send, m);
                acc[i] = (up ? acc[i + m] : acc[i]) + got;
            }
        }
        acc[0] += __shfl_xor_sync(0xffffffffu, acc[0], 16);
        // lane L holds warp total of acc[L&15]

        if (lane < 16) red[w][lane] = acc[0];    // warps 0-7: rh=0, 8-15: rh=1
        __syncthreads();
        if (t < 32) {
            const int bl = t >> 3, r = t & 7;
            const int rh2 = r >> 2, rr = r & 3;
            float s = 0.0f;
#pragma unroll
            for (int w2 = 0; w2 < 8; w2++) s += red[rh2 * 8 + w2][bl * 4 + rr];
            g_u_part[half][(bbase + bl) * RANK + r] = s;
        }
    }

    grid_barrier();

    // ===================== Phase 2: new_h (exact fp32) ====================
    {
        const int jt = blockIdx.x & 15;          // 16 j-tiles of 512
        const int bc = blockIdx.x >> 4;          // 16 batch chunks of 32
        const int b0 = bc * 32;
        const int j = jt * 512 + t;              // one j-column per thread

        // stage [input | u] per batch row: comb[bi][0..15]=input, [16..23]=u
        for (int v = t; v < 32 * 24; v += TPB) {
            const int bi = v / 24, c = v - bi * 24;
            float val;
            if (c < NIN) {
                val = input[(b0 + bi) * NIN + c];
            } else {
                const int idx = (b0 + bi) * RANK + (c - NIN);
                val = (g_u_part[0][idx] + g_u_part[1][idx]) * (1.0f / (float)HID);
            }
            comb[bi][c] = val;
        }

        ull wj[8], lj[4];
        {
            const ull* wr = (const ull*)(Win + j * NIN);
#pragma unroll
            for (int i = 0; i < 8; i++) wj[i] = wr[i];
            const ull* lr = (const ull*)(L + j * RANK);
#pragma unroll
            for (int r = 0; r < 4; r++) lj[r] = lr[r];
        }
        __syncthreads();

#pragma unroll 4
        for (int bi = 0; bi < 32; bi++) {
            const int b = b0 + bi;

            // 6x LDS.128 broadcast: 24 floats = 12 f32x2 operand pairs
            union { float4 f4[6]; ull p[12]; } cb;
            const float4* cp = (const float4*)&comb[bi][0];
#pragma unroll
            for (int q = 0; q < 6; q++) cb.f4[q] = cp[q];

            float h = hidden[b * HID + j];

            ull acc = 0ULL;
#pragma unroll
            for (int i = 0; i < 8; i++) ffma2(acc, wj[i], cb.p[i]);
#pragma unroll
            for (int r = 0; r < 4; r++) ffma2(acc, lj[r], cb.p[8 + r]);
            float lo, hi;
            unpack2(lo, hi, acc);

            nh[b * HID + j] = fmaf(0.1f, lo + hi, 0.9f * h);
        }
    }

    grid_barrier();

    // ====== Phase 3: output (2 rows per block, full H, f32x2 accum) =======
    {
        const int bbase = blockIdx.x * 2;

        ull accp[8];                             // accp[bl*4+o] = (even-j, odd-j)
#pragma unroll
        for (int i = 0; i < 8; i++) accp[i] = 0ULL;

#pragma unroll
        for (int it = 0; it < 4; it++) {
            const int j = it * 2048 + t * 4;
            float4 x0 = *(const float4*)(nh + bbase * HID + j);
            float4 x1 = *(const float4*)(nh + (bbase + 1) * HID + j);
            ull thp[2][2];
            thp[0][0] = pack2(__tanhf(x0.x), __tanhf(x0.y));
            thp[0][1] = pack2(__tanhf(x0.z), __tanhf(x0.w));
            thp[1][0] = pack2(__tanhf(x1.x), __tanhf(x1.y));
            thp[1][1] = pack2(__tanhf(x1.z), __tanhf(x1.w));

#pragma unroll
            for (int o = 0; o < 4; o++) {
                union { float4 f; ull p[2]; } w4;
                w4.f = *(const float4*)(Wout + o * HID + j);
#pragma unroll
                for (int bl = 0; bl < 2; bl++) {
                    ffma2(accp[bl * 4 + o], thp[bl][0], w4.p[0]);
                    ffma2(accp[bl * 4 + o], thp[bl][1], w4.p[1]);
                }
            }
        }

        float acc[8];
#pragma unroll
        for (int i = 0; i < 8; i++) {
            float lo, hi;
            unpack2(lo, hi, accp[i]);
            acc[i] = lo + hi;
        }

        // fold 8 values over lane bits 0..2, then reduce bits 3,4
#pragma unroll
        for (int m = 4; m >= 1; m >>= 1) {
            const bool up = (lane & m) != 0;
#pragma unroll
            for (int i = 0; i < m; i++) {
                float send = up ? acc[i] : acc[i + m];
                float got = __shfl_xor_sync(0xffffffffu, send, m);
                acc[i] = (up ? acc[i + m] : acc[i]) + got;
            }
        }
        acc[0] += __shfl_xor_sync(0xffffffffu, acc[0], 8);
        acc[0] += __shfl_xor_sync(0xffffffffu, acc[0], 16);

        __syncthreads();   // red[] reuse
        if (lane < 8) red[w][lane] = acc[0];
        __syncthreads();
        if (t < 8) {
            float s = 0.0f;
#pragma unroll
            for (int w2 = 0; w2 < 16; w2++) s += red[w2][t];
            out[(bbase + (t >> 2)) * NOUT + (t & 3)] = s * (1.0f / (float)HID);
        }
    }
}

extern "C" void kernel_launch(void* const* d_in, const int* in_sizes, int n_in,
                              void* d_out, int out_size) {
    const float* input  = (const float*)d_in[0];  // [512,16]
    const float* hidden = (const float*)d_in[1];  // [512,8192]
    const float* Win    = (const float*)d_in[2];  // [8192,16]
    const float* L      = (const float*)d_in[3];  // [8192,8]
    const float* R      = (const float*)d_in[4];  // [8,8192]
    const float* Wout   = (const float*)d_in[5];  // [4,8192]

    float* out = (float*)d_out;                   // [512,4] then [512,8192]
    float* nh  = out + BATCH * NOUT;

    k_fused<<<GRID, TPB>>>(input, hidden, Win, L, R, Wout, nh, out);
}

// round 13
// speedup vs baseline: 1.0102x; 1.0102x over previous
#include <cuda_runtime.h>

#define HID 8192
#define BATCH 512
#define NIN 16
#define RANK 8
#define NOUT 4
#define GRID 256
#define TPB 512

__device__ float g_u[BATCH * RANK];   // final u, written by phase 1
__device__ unsigned int g_bar;        // monotone ticket counter (replay-safe)

typedef unsigned long long ull;

__device__ __forceinline__ void ffma2(ull& d, ull a, ull b) {
    asm("fma.rn.f32x2 %0, %1, %2, %0;" : "+l"(d) : "l"(a), "l"(b));
}
__device__ __forceinline__ void unpack2(float& lo, float& hi, ull v) {
    asm("mov.b64 {%0, %1}, %2;" : "=f"(lo), "=f"(hi) : "l"(v));
}

__device__ __forceinline__ void grid_barrier() {
    __syncthreads();
    if (threadIdx.x == 0) {
        __threadfence();
        unsigned int old = atomicAdd(&g_bar, 1u);
        unsigned int target = (old / GRID + 1u) * GRID;
        while ((int)(*(volatile unsigned int*)&g_bar - target) < 0)
            __nanosleep(32);
        __threadfence();
    }
    __syncthreads();
}

__global__ void __launch_bounds__(TPB, 2) k_fused(const float* __restrict__ input,
                                                  const float* __restrict__ hidden,
                                                  const float* __restrict__ Win,
                                                  const float* __restrict__ L,
                                                  const float* __restrict__ R,
                                                  const float* __restrict__ Wout,
                                                  float* __restrict__ nh,
                                                  float* __restrict__ out) {
    const int t = threadIdx.x;
    const int lane = t & 31, w = t >> 5;    // 16 warps

    __shared__ float red[16][16];
    __shared__ __align__(16) float comb[32][24];   // phase 2: [input(16) | u(8)]

    // ========== Phase 1: u for 2 batch rows, full H, no duplication =======
    {
        const int bbase = blockIdx.x * 2;

        float acc[16];                            // acc[bl*8 + r]
#pragma unroll
        for (int i = 0; i < 16; i++) acc[i] = 0.0f;

#pragma unroll
        for (int it = 0; it < 4; it++) {
            const int j = it * 2048 + t * 4;
            float4 h0 = *(const float4*)(hidden + bbase * HID + j);
            float4 h1 = *(const float4*)(hidden + (bbase + 1) * HID + j);
            float th[2][4];
            th[0][0] = __tanhf(h0.x); th[0][1] = __tanhf(h0.y);
            th[0][2] = __tanhf(h0.z); th[0][3] = __tanhf(h0.w);
            th[1][0] = __tanhf(h1.x); th[1][1] = __tanhf(h1.y);
            th[1][2] = __tanhf(h1.z); th[1][3] = __tanhf(h1.w);

#pragma unroll
            for (int r = 0; r < 8; r++) {
                float4 rv = *(const float4*)(R + r * HID + j);
#pragma unroll
                for (int bl = 0; bl < 2; bl++) {
                    float a = acc[bl * 8 + r];
                    a = fmaf(th[bl][0], rv.x, a);
                    a = fmaf(th[bl][1], rv.y, a);
                    a = fmaf(th[bl][2], rv.z, a);
                    a = fmaf(th[bl][3], rv.w, a);
                    acc[bl * 8 + r] = a;
                }
            }
        }

        // fold 16 values over lane bits 0..3 (15 SHFL), then reduce bit 4
#pragma unroll
        for (int m = 8; m >= 1; m >>= 1) {
            const bool up = (lane & m) != 0;
#pragma unroll
            for (int i = 0; i < m; i++) {
                float send = up ? acc[i] : acc[i + m];
                float got = __shfl_xor_sync(0xffffffffu, send, m);
                acc[i] = (up ? acc[i + m] : acc[i]) + got;
            }
        }
        acc[0] += __shfl_xor_sync(0xffffffffu, acc[0], 16);
        // lane L holds warp total of acc[L&15]

        if (lane < 16) red[w][lane] = acc[0];
        __syncthreads();
        if (t < 16) {
            float s = 0.0f;
#pragma unroll
            for (int w2 = 0; w2 < 16; w2++) s += red[w2][t];
            // L: bl = L>>3, r = L&7 -> (bbase+bl)*RANK + r = bbase*RANK + L
            g_u[bbase * RANK + t] = s * (1.0f / (float)HID);
        }
    }

    grid_barrier();

    // ===================== Phase 2: new_h (exact fp32) ====================
    {
        const int jt = blockIdx.x & 15;          // 16 j-tiles of 512
        const int bc = blockIdx.x >> 4;          // 16 batch chunks of 32
        const int b0 = bc * 32;
        const int j = jt * 512 + t;              // one j-column per thread

        // stage [input | u] per batch row: comb[bi][0..15]=input, [16..23]=u
        for (int v = t; v < 32 * 24; v += TPB) {
            const int bi = v / 24, c = v - bi * 24;
            comb[bi][c] = (c < NIN) ? input[(b0 + bi) * NIN + c]
                                    : g_u[(b0 + bi) * RANK + (c - NIN)];
        }

        ull wj[8], lj[4];
        {
            const ull* wr = (const ull*)(Win + j * NIN);
#pragma unroll
            for (int i = 0; i < 8; i++) wj[i] = wr[i];
            const ull* lr = (const ull*)(L + j * RANK);
#pragma unroll
            for (int r = 0; r < 4; r++) lj[r] = lr[r];
        }
        __syncthreads();

#pragma unroll 4
        for (int bi = 0; bi < 32; bi++) {
            const int b = b0 + bi;

            // 6x LDS.128 broadcast: 24 floats = 12 f32x2 operand pairs
            union { float4 f4[6]; ull p[12]; } cb;
            const float4* cp = (const float4*)&comb[bi][0];
#pragma unroll
            for (int q = 0; q < 6; q++) cb.f4[q] = cp[q];

            float h = hidden[b * HID + j];

            // two independent chains (6+6) for ILP
            ull acc0 = 0ULL, acc1 = 0ULL;
#pragma unroll
            for (int i = 0; i < 4; i++) ffma2(acc0, wj[i], cb.p[i]);
#pragma unroll
            for (int i = 4; i < 8; i++) ffma2(acc1, wj[i], cb.p[i]);
#pragma unroll
            for (int r = 0; r < 2; r++) ffma2(acc0, lj[r], cb.p[8 + r]);
#pragma unroll
            for (int r = 2; r < 4; r++) ffma2(acc1, lj[r], cb.p[8 + r]);

            float lo0, hi0, lo1, hi1;
            unpack2(lo0, hi0, acc0);
            unpack2(lo1, hi1, acc1);
            const float res = (lo0 + hi0) + (lo1 + hi1);

            nh[b * HID + j] = fmaf(0.1f, res, 0.9f * h);
        }
    }

    grid_barrier();

    // ============ Phase 3: output (2 rows per block, full H) ==============
    {
        const int bbase = blockIdx.x * 2;

        float acc[8];
#pragma unroll
        for (int i = 0; i < 8; i++) acc[i] = 0.0f;

#pragma unroll
        for (int it = 0; it < 4; it++) {
            const int j = it * 2048 + t * 4;
            float4 x0 = *(const float4*)(nh + bbase * HID + j);
            float4 x1 = *(const float4*)(nh + (bbase + 1) * HID + j);
            float th[2][4];
            th[0][0] = __tanhf(x0.x); th[0][1] = __tanhf(x0.y);
            th[0][2] = __tanhf(x0.z); th[0][3] = __tanhf(x0.w);
            th[1][0] = __tanhf(x1.x); th[1][1] = __tanhf(x1.y);
            th[1][2] = __tanhf(x1.z); th[1][3] = __tanhf(x1.w);

#pragma unroll
            for (int o = 0; o < 4; o++) {
                float4 w4 = *(const float4*)(Wout + o * HID + j);
#pragma unroll
                for (int bl = 0; bl < 2; bl++) {
                    float a = acc[bl * 4 + o];
                    a = fmaf(th[bl][0], w4.x, a);
                    a = fmaf(th[bl][1], w4.y, a);
                    a = fmaf(th[bl][2], w4.z, a);
                    a = fmaf(th[bl][3], w4.w, a);
                    acc[bl * 4 + o] = a;
                }
            }
        }

        // fold 8 values over lane bits 0..2, then reduce bits 3,4
#pragma unroll
        for (int m = 4; m >= 1; m >>= 1) {
            const bool up = (lane & m) != 0;
#pragma unroll
            for (int i = 0; i < m; i++) {
                float send = up ? acc[i] : acc[i + m];
                float got = __shfl_xor_sync(0xffffffffu, send, m);
                acc[i] = (up ? acc[i + m] : acc[i]) + got;
            }
        }
        acc[0] += __shfl_xor_sync(0xffffffffu, acc[0], 8);
        acc[0] += __shfl_xor_sync(0xffffffffu, acc[0], 16);

        __syncthreads();   // red[] reuse
        if (lane < 8) red[w][lane] = acc[0];
        __syncthreads();
        if (t < 8) {
            float s = 0.0f;
#pragma unroll
            for (int w2 = 0; w2 < 16; w2++) s += red[w2][t];
            out[(bbase + (t >> 2)) * NOUT + (t & 3)] = s * (1.0f / (float)HID);
        }
    }
}

extern "C" void kernel_launch(void* const* d_in, const int* in_sizes, int n_in,
                              void* d_out, int out_size) {
    const float* input  = (const float*)d_in[0];  // [512,16]
    const float* hidden = (const float*)d_in[1];  // [512,8192]
    const float* Win    = (const float*)d_in[2];  // [8192,16]
    const float* L      = (const float*)d_in[3];  // [8192,8]
    const float* R      = (const float*)d_in[4];  // [8,8192]
    const float* Wout   = (const float*)d_in[5];  // [4,8192]

    float* out = (float*)d_out;                   // [512,4] then [512,8192]
    float* nh  = out + BATCH * NOUT;

    k_fused<<<GRID, TPB>>>(input, hidden, Win, L, R, Wout, nh, out);
}